// round 2
// baseline (speedup 1.0000x reference)
#include <cuda_runtime.h>

#define NN 50000
#define NE 600000
#define D  128
#define NL 6

// ---------------- scratch (device globals; no allocation allowed) ----------------
__device__ float g_buf[2][NN * D];   // ping-pong hidden states
__device__ float g_agg[NN * D];      // mean-aggregated neighbor features
__device__ int   g_rowptr[NN + 1];
__device__ int   g_cursor[NN];
__device__ int   g_deg[NN];
__device__ int   g_esrc[NE];

// ---------------- f32x2 packed math (sm_103a) ----------------
__device__ __forceinline__ unsigned long long fma2(unsigned long long a,
                                                   unsigned long long b,
                                                   unsigned long long c) {
    unsigned long long d;
    asm("fma.rn.f32x2 %0, %1, %2, %3;" : "=l"(d) : "l"(a), "l"(b), "l"(c));
    return d;
}
__device__ __forceinline__ unsigned long long packdup(float x) {
    unsigned long long r;
    asm("mov.b64 %0, {%1, %1};" : "=l"(r) : "f"(x));
    return r;
}
__device__ __forceinline__ void unpack2(unsigned long long v, float& lo, float& hi) {
    asm("mov.b64 {%0, %1}, %2;" : "=f"(lo), "=f"(hi) : "l"(v));
}

// ---------------- CSR construction ----------------
__global__ void k_zero_deg() {
    int i = blockIdx.x * blockDim.x + threadIdx.x;
    if (i < NN) g_deg[i] = 0;
}

__global__ void k_count(const int* __restrict__ ei) {
    int i = blockIdx.x * blockDim.x + threadIdx.x;
    if (i < NE) atomicAdd(&g_deg[ei[NE + i]], 1);
}

// single-block scan: g_rowptr = exclusive prefix of g_deg
__global__ void k_scan() {
    __shared__ int warpsum[32];
    __shared__ int s_off;
    int tid = threadIdx.x, lane = tid & 31, wid = tid >> 5;
    if (tid == 0) { s_off = 0; g_rowptr[0] = 0; }
    for (int base = 0; base < NN; base += 1024) {
        __syncthreads();
        int off = s_off;
        int i = base + tid;
        int v = (i < NN) ? g_deg[i] : 0;
        int incl = v;
        #pragma unroll
        for (int d2 = 1; d2 < 32; d2 <<= 1) {
            int t = __shfl_up_sync(0xffffffffu, incl, d2);
            if (lane >= d2) incl += t;
        }
        if (lane == 31) warpsum[wid] = incl;
        __syncthreads();
        if (wid == 0) {
            int s = warpsum[lane];
            int x = s;
            #pragma unroll
            for (int d2 = 1; d2 < 32; d2 <<= 1) {
                int t = __shfl_up_sync(0xffffffffu, x, d2);
                if (lane >= d2) x += t;
            }
            warpsum[lane] = x - s;  // exclusive warp offsets
        }
        __syncthreads();
        incl += warpsum[wid];
        if (i < NN) g_rowptr[i + 1] = off + incl;
        if (tid == 1023) s_off = off + incl;
    }
}

__global__ void k_initcursor() {
    int i = blockIdx.x * blockDim.x + threadIdx.x;
    if (i < NN) g_cursor[i] = g_rowptr[i];
}

__global__ void k_fill(const int* __restrict__ ei) {
    int i = blockIdx.x * blockDim.x + threadIdx.x;
    if (i < NE) {
        int dst = ei[NE + i];
        int pos = atomicAdd(&g_cursor[dst], 1);
        g_esrc[pos] = ei[i];
    }
}

// ---------------- mean aggregation: warp per node ----------------
__global__ void k_agg(const float* __restrict__ x, int use_x, int pin) {
    int gw = (blockIdx.x * blockDim.x + threadIdx.x) >> 5;
    if (gw >= NN) return;
    const float* hin = use_x ? x : g_buf[pin];
    int lane = threadIdx.x & 31;
    int off = lane << 2;
    int beg = g_rowptr[gw], end = g_rowptr[gw + 1];
    float ax = 0.f, ay = 0.f, az = 0.f, aw = 0.f;
    int e = beg;
    for (; e + 4 <= end; e += 4) {
        int s0 = __ldg(&g_esrc[e + 0]);
        int s1 = __ldg(&g_esrc[e + 1]);
        int s2 = __ldg(&g_esrc[e + 2]);
        int s3 = __ldg(&g_esrc[e + 3]);
        float4 v0 = __ldg((const float4*)(hin + (long)s0 * D + off));
        float4 v1 = __ldg((const float4*)(hin + (long)s1 * D + off));
        float4 v2 = __ldg((const float4*)(hin + (long)s2 * D + off));
        float4 v3 = __ldg((const float4*)(hin + (long)s3 * D + off));
        ax += v0.x + v1.x + v2.x + v3.x;
        ay += v0.y + v1.y + v2.y + v3.y;
        az += v0.z + v1.z + v2.z + v3.z;
        aw += v0.w + v1.w + v2.w + v3.w;
    }
    for (; e < end; ++e) {
        int s0 = __ldg(&g_esrc[e]);
        float4 v0 = __ldg((const float4*)(hin + (long)s0 * D + off));
        ax += v0.x; ay += v0.y; az += v0.z; aw += v0.w;
    }
    float inv = 1.0f / fmaxf((float)(end - beg), 1.0f);
    float4 r = make_float4(ax * inv, ay * inv, az * inv, aw * inv);
    *(float4*)(g_agg + (long)gw * D + off) = r;
}

// ---------------- fused layer GEMM: out = relu([agg|h] @ [Wl;Wr] + bl) ----------------
// M=50000 (64/block), N=128, K=256. 256 threads, microtile 4Mx8N via f32x2.
#define SMEM_FLOATS (256 * 128 + 16 * 68)

__global__ void k_gemm(const float* __restrict__ x, int use_x, int pin, int pout,
                       const float* __restrict__ Wl, const float* __restrict__ Wr,
                       const float* __restrict__ bl) {
    extern __shared__ float smem[];
    float* sB = smem;                 // [256][128] stacked weights, k-major
    float* sA = smem + 256 * 128;     // [16][68]   A tile transposed (padded)
    const float* hin = use_x ? x : g_buf[pin];
    float* out = g_buf[pout];
    int tid = threadIdx.x;

    // stage full weight stack into smem (128 KB)
    #pragma unroll
    for (int i = 0; i < 32; i++) {
        int f4 = tid + i * 256;          // float4 index, 0..8191
        int k  = f4 >> 5;
        int nc = (f4 & 31) << 2;
        const float* sp = (k < D) ? (Wl + k * D + nc) : (Wr + (k - D) * D + nc);
        *(float4*)&sB[k * D + nc] = __ldg((const float4*)sp);
    }

    int tm = tid & 15;      // 16 threads along M (4 rows each)
    int tn = tid >> 4;      // 16 threads along N (8 cols each)
    int m0 = blockIdx.x * 64;

    unsigned long long acc[4][4];
    #pragma unroll
    for (int i = 0; i < 4; i++)
        #pragma unroll
        for (int p = 0; p < 4; p++) acc[i][p] = 0ull;

    int lr = tid >> 2;            // row 0..63 for A staging
    int lk = (tid & 3) << 2;      // k offset 0,4,8,12
    int grow = m0 + lr;

    #pragma unroll 1
    for (int kt = 0; kt < 16; kt++) {
        int kbase = kt << 4;
        float4 av = make_float4(0.f, 0.f, 0.f, 0.f);
        if (grow < NN) {
            const float* src = (kt < 8)
                ? (g_agg + (long)grow * D + kbase + lk)
                : (hin   + (long)grow * D + (kbase - D) + lk);
            av = __ldg((const float4*)src);
        }
        __syncthreads();
        sA[(lk + 0) * 68 + lr] = av.x;
        sA[(lk + 1) * 68 + lr] = av.y;
        sA[(lk + 2) * 68 + lr] = av.z;
        sA[(lk + 3) * 68 + lr] = av.w;
        __syncthreads();
        #pragma unroll
        for (int kk = 0; kk < 16; kk++) {
            float4 a = *(const float4*)&sA[kk * 68 + (tm << 2)];
            const unsigned long long* b64 =
                (const unsigned long long*)&sB[(kbase + kk) * D + (tn << 3)];
            unsigned long long b0 = b64[0], b1 = b64[1], b2 = b64[2], b3 = b64[3];
            unsigned long long a0 = packdup(a.x), a1 = packdup(a.y),
                               a2 = packdup(a.z), a3 = packdup(a.w);
            acc[0][0] = fma2(a0, b0, acc[0][0]); acc[0][1] = fma2(a0, b1, acc[0][1]);
            acc[0][2] = fma2(a0, b2, acc[0][2]); acc[0][3] = fma2(a0, b3, acc[0][3]);
            acc[1][0] = fma2(a1, b0, acc[1][0]); acc[1][1] = fma2(a1, b1, acc[1][1]);
            acc[1][2] = fma2(a1, b2, acc[1][2]); acc[1][3] = fma2(a1, b3, acc[1][3]);
            acc[2][0] = fma2(a2, b0, acc[2][0]); acc[2][1] = fma2(a2, b1, acc[2][1]);
            acc[2][2] = fma2(a2, b2, acc[2][2]); acc[2][3] = fma2(a2, b3, acc[2][3]);
            acc[3][0] = fma2(a3, b0, acc[3][0]); acc[3][1] = fma2(a3, b1, acc[3][1]);
            acc[3][2] = fma2(a3, b2, acc[3][2]); acc[3][3] = fma2(a3, b3, acc[3][3]);
        }
    }

    float bvals[8];
    *(float4*)&bvals[0] = __ldg((const float4*)&bl[(tn << 3)]);
    *(float4*)&bvals[4] = __ldg((const float4*)&bl[(tn << 3) + 4]);

    #pragma unroll
    for (int i = 0; i < 4; i++) {
        int row = m0 + (tm << 2) + i;
        if (row < NN) {
            float o[8];
            #pragma unroll
            for (int p = 0; p < 4; p++) {
                float lo, hi;
                unpack2(acc[i][p], lo, hi);
                o[2 * p]     = fmaxf(lo + bvals[2 * p], 0.0f);
                o[2 * p + 1] = fmaxf(hi + bvals[2 * p + 1], 0.0f);
            }
            float* op = out + (long)row * D + (tn << 3);
            *(float4*)op       = *(float4*)&o[0];
            *(float4*)(op + 4) = *(float4*)&o[4];
        }
    }
}

// ---------------- final FC [128 -> 2]: warp per node ----------------
__global__ void k_fc(const float* __restrict__ fcW, const float* __restrict__ fcb,
                     float* __restrict__ out) {
    int gw = (blockIdx.x * blockDim.x + threadIdx.x) >> 5;
    if (gw >= NN) return;
    int lane = threadIdx.x & 31;
    const float* h = g_buf[1] + (long)gw * D;
    float4 v = *(const float4*)(h + (lane << 2));
    int k0 = lane << 2;
    float4 w01 = __ldg((const float4*)(fcW + k0 * 2));
    float4 w23 = __ldg((const float4*)(fcW + k0 * 2 + 4));
    float a0 = v.x * w01.x + v.y * w01.z + v.z * w23.x + v.w * w23.z;
    float a1 = v.x * w01.y + v.y * w01.w + v.z * w23.y + v.w * w23.w;
    #pragma unroll
    for (int d2 = 16; d2; d2 >>= 1) {
        a0 += __shfl_xor_sync(0xffffffffu, a0, d2);
        a1 += __shfl_xor_sync(0xffffffffu, a1, d2);
    }
    if (lane == 0) {
        out[2 * gw]     = a0 + __ldg(&fcb[0]);
        out[2 * gw + 1] = a1 + __ldg(&fcb[1]);
    }
}

// ---------------- launch ----------------
extern "C" void kernel_launch(void* const* d_in, const int* in_sizes, int n_in,
                              void* d_out, int out_size) {
    const float* x   = (const float*)d_in[0];
    const int*   ei  = (const int*)d_in[1];
    const float* Wl  = (const float*)d_in[2];
    const float* Wr  = (const float*)d_in[3];
    const float* bl  = (const float*)d_in[4];
    const float* fcW = (const float*)d_in[5];
    const float* fcb = (const float*)d_in[6];
    float* out = (float*)d_out;

    const int smem_bytes = SMEM_FLOATS * sizeof(float);  // 135424
    cudaFuncSetAttribute(k_gemm, cudaFuncAttributeMaxDynamicSharedMemorySize, smem_bytes);

    k_zero_deg<<<(NN + 255) / 256, 256>>>();
    k_count<<<(NE + 255) / 256, 256>>>(ei);
    k_scan<<<1, 1024>>>();
    k_initcursor<<<(NN + 255) / 256, 256>>>();
    k_fill<<<(NE + 255) / 256, 256>>>(ei);

    for (int l = 0; l < NL; l++) {
        int use_x = (l == 0) ? 1 : 0;
        int pout  = l & 1;
        int pin   = use_x ? 0 : (pout ^ 1);
        k_agg<<<(NN * 32 + 255) / 256, 256>>>(x, use_x, pin);
        k_gemm<<<(NN + 63) / 64, 256, smem_bytes>>>(x, use_x, pin, pout,
                                                    Wl + (long)l * D * D,
                                                    Wr + (long)l * D * D,
                                                    bl + (long)l * D);
    }
    k_fc<<<(NN * 32 + 255) / 256, 256>>>(fcW, fcb, out);
}

// round 6
// speedup vs baseline: 1.8153x; 1.8153x over previous
#include <cuda_runtime.h>
#include <cuda_bf16.h>
#include <cstdint>

#define NN 50000
#define NE 600000
#define D  128
#define NL 6
#define MT 128
#define NTILES ((NN + MT - 1) / MT)   // 391
#define SREG 136                      // smem row stride in bf16 (128 + 8 pad)

// ---------------- scratch (device globals; no allocation allowed) ----------------
__device__ float g_h[NN * D];                    // fp32 hidden state (for gather + FC)
__device__ __nv_bfloat16 g_Ahi[NN * 256];        // A = [agg | h] bf16 hi
__device__ __nv_bfloat16 g_Alo[NN * 256];        // A lo residual
__device__ __nv_bfloat16 g_Bhi[NL * 128 * 256];  // B[n][k] = W[k][n], bf16 hi
__device__ __nv_bfloat16 g_Blo[NL * 128 * 256];  // lo residual
__device__ int g_rowptr[NN + 1];
__device__ int g_cursor[NN];
__device__ int g_deg[NN];
__device__ int g_esrc[NE];

// ---------------- helpers ----------------
__device__ __forceinline__ void mma16816(float* c, const uint32_t* a, const uint32_t* b) {
    asm volatile("mma.sync.aligned.m16n8k16.row.col.f32.bf16.bf16.f32 "
                 "{%0,%1,%2,%3}, {%4,%5,%6,%7}, {%8,%9}, {%0,%1,%2,%3};"
                 : "+f"(c[0]), "+f"(c[1]), "+f"(c[2]), "+f"(c[3])
                 : "r"(a[0]), "r"(a[1]), "r"(a[2]), "r"(a[3]), "r"(b[0]), "r"(b[1]));
}
__device__ __forceinline__ uint32_t pack_bf2(float x, float y) {
    __nv_bfloat162 h = __float22bfloat162_rn(make_float2(x, y));
    return *(uint32_t*)&h;
}
// split pair (x,y) -> hi packed, lo packed
__device__ __forceinline__ void split2(float x, float y, uint32_t& hi, uint32_t& lo) {
    __nv_bfloat16 hx = __float2bfloat16(x);
    __nv_bfloat16 hy = __float2bfloat16(y);
    hi = pack_bf2(x, y);
    lo = pack_bf2(x - __bfloat162float(hx), y - __bfloat162float(hy));
}

// ---------------- CSR construction ----------------
__global__ void k_zero_deg() {
    int i = blockIdx.x * blockDim.x + threadIdx.x;
    if (i < NN) g_deg[i] = 0;
}
__global__ void k_count(const int* __restrict__ ei) {
    int i = blockIdx.x * blockDim.x + threadIdx.x;
    if (i < NE) atomicAdd(&g_deg[ei[NE + i]], 1);
}
__global__ void k_scan() {
    __shared__ int warpsum[32];
    __shared__ int s_off;
    int tid = threadIdx.x, lane = tid & 31, wid = tid >> 5;
    if (tid == 0) { s_off = 0; g_rowptr[0] = 0; }
    for (int base = 0; base < NN; base += 1024) {
        __syncthreads();
        int off = s_off;
        int i = base + tid;
        int v = (i < NN) ? g_deg[i] : 0;
        int incl = v;
        #pragma unroll
        for (int d2 = 1; d2 < 32; d2 <<= 1) {
            int t = __shfl_up_sync(0xffffffffu, incl, d2);
            if (lane >= d2) incl += t;
        }
        if (lane == 31) warpsum[wid] = incl;
        __syncthreads();
        if (wid == 0) {
            int s = warpsum[lane];
            int x2 = s;
            #pragma unroll
            for (int d2 = 1; d2 < 32; d2 <<= 1) {
                int t = __shfl_up_sync(0xffffffffu, x2, d2);
                if (lane >= d2) x2 += t;
            }
            warpsum[lane] = x2 - s;
        }
        __syncthreads();
        incl += warpsum[wid];
        if (i < NN) g_rowptr[i + 1] = off + incl;
        if (tid == 1023) s_off = off + incl;
    }
}
__global__ void k_initcursor() {
    int i = blockIdx.x * blockDim.x + threadIdx.x;
    if (i < NN) g_cursor[i] = g_rowptr[i];
}
__global__ void k_fill(const int* __restrict__ ei) {
    int i = blockIdx.x * blockDim.x + threadIdx.x;
    if (i < NE) {
        int dst = ei[NE + i];
        int pos = atomicAdd(&g_cursor[dst], 1);
        g_esrc[pos] = ei[i];
    }
}

// ---------------- weight transpose + split (once per launch) ----------------
// g_B*[l][n][k] = split(W[k][n]),  W = Wl for k<128 else Wr
__global__ void k_prepw(const float* __restrict__ Wl, const float* __restrict__ Wr) {
    int idx = blockIdx.x * blockDim.x + threadIdx.x;
    if (idx >= NL * 128 * 256) return;
    int l = idx >> 15;
    int r = idx & 32767;
    int n = r >> 8;
    int k = r & 255;
    const float* W = (k < D) ? (Wl + (long)l * D * D) : (Wr + (long)l * D * D);
    float v = __ldg(&W[(k & 127) * D + n]);
    __nv_bfloat16 hi = __float2bfloat16(v);
    g_Bhi[idx] = hi;
    g_Blo[idx] = __float2bfloat16(v - __bfloat162float(hi));
}

// ---------------- split x into A cols [128,256) (once) ----------------
__global__ void k_splitx(const float* __restrict__ x) {
    int idx = blockIdx.x * blockDim.x + threadIdx.x;
    if (idx >= NN * 32) return;
    int row = idx >> 5;
    int c = (idx & 31) << 2;
    float4 v = __ldg((const float4*)(x + (long)row * D + c));
    uint32_t h0, l0, h1, l1;
    split2(v.x, v.y, h0, l0);
    split2(v.z, v.w, h1, l1);
    uint32_t* ph = (uint32_t*)(g_Ahi + (long)row * 256 + 128 + c);
    uint32_t* pl = (uint32_t*)(g_Alo + (long)row * 256 + 128 + c);
    ph[0] = h0; ph[1] = h1;
    pl[0] = l0; pl[1] = l1;
}

// ---------------- mean aggregation: warp per node, writes split A cols [0,128) ----------------
__global__ void k_agg(const float* __restrict__ x, int use_x) {
    int gw = (blockIdx.x * blockDim.x + threadIdx.x) >> 5;
    if (gw >= NN) return;
    const float* hin = use_x ? x : g_h;
    int lane = threadIdx.x & 31;
    int off = lane << 2;
    int beg = g_rowptr[gw], end = g_rowptr[gw + 1];
    float ax = 0.f, ay = 0.f, az = 0.f, aw = 0.f;
    int e = beg;
    for (; e + 4 <= end; e += 4) {
        int s0 = __ldg(&g_esrc[e + 0]);
        int s1 = __ldg(&g_esrc[e + 1]);
        int s2 = __ldg(&g_esrc[e + 2]);
        int s3 = __ldg(&g_esrc[e + 3]);
        float4 v0 = __ldg((const float4*)(hin + (long)s0 * D + off));
        float4 v1 = __ldg((const float4*)(hin + (long)s1 * D + off));
        float4 v2 = __ldg((const float4*)(hin + (long)s2 * D + off));
        float4 v3 = __ldg((const float4*)(hin + (long)s3 * D + off));
        ax += v0.x + v1.x + v2.x + v3.x;
        ay += v0.y + v1.y + v2.y + v3.y;
        az += v0.z + v1.z + v2.z + v3.z;
        aw += v0.w + v1.w + v2.w + v3.w;
    }
    for (; e < end; ++e) {
        int s0 = __ldg(&g_esrc[e]);
        float4 v0 = __ldg((const float4*)(hin + (long)s0 * D + off));
        ax += v0.x; ay += v0.y; az += v0.z; aw += v0.w;
    }
    float inv = 1.0f / fmaxf((float)(end - beg), 1.0f);
    ax *= inv; ay *= inv; az *= inv; aw *= inv;
    uint32_t h0, l0, h1, l1;
    split2(ax, ay, h0, l0);
    split2(az, aw, h1, l1);
    uint32_t* ph = (uint32_t*)(g_Ahi + (long)gw * 256 + off);
    uint32_t* pl = (uint32_t*)(g_Alo + (long)gw * 256 + off);
    ph[0] = h0; ph[1] = h1;
    pl[0] = l0; pl[1] = l1;
}

// ---------------- tensor-core GEMM: h = relu(A @ B^T + bl), A 128x256, B 128x256 ----------------
// 256 threads = 8 warps, warp grid 2(m) x 4(n), warp tile 64x32, frag m16n8k16.
// 3-term bf16 split: hihi + hilo + lohi.
#define SM_A_HI 0
#define SM_A_LO (128 * SREG)
#define SM_B_HI (2 * 128 * SREG)
#define SM_B_LO (3 * 128 * SREG)
#define SM_TOT_BF (4 * 128 * SREG)   // 69632 bf16 = 139264 bytes

__global__ void __launch_bounds__(256, 1)
k_gemm_mma(int layer, int write_split, const float* __restrict__ bl) {
    extern __shared__ __nv_bfloat16 smem[];
    __nv_bfloat16* sAhi = smem + SM_A_HI;
    __nv_bfloat16* sAlo = smem + SM_A_LO;
    __nv_bfloat16* sBhi = smem + SM_B_HI;
    __nv_bfloat16* sBlo = smem + SM_B_LO;

    int tid = threadIdx.x;
    int lane = tid & 31, wid = tid >> 5;
    int warp_m = wid >> 2, warp_n = wid & 3;
    int m0 = blockIdx.x * MT;
    int g = lane >> 2, t = lane & 3;

    float acc[4][4][4];
    #pragma unroll
    for (int i = 0; i < 4; i++)
        #pragma unroll
        for (int j = 0; j < 4; j++)
            #pragma unroll
            for (int p = 0; p < 4; p++) acc[i][j][p] = 0.f;

    const __nv_bfloat16* gB_hi = g_Bhi + (long)layer * 128 * 256;
    const __nv_bfloat16* gB_lo = g_Blo + (long)layer * 128 * 256;

    #pragma unroll 1
    for (int chunk = 0; chunk < 2; chunk++) {
        int kbase = chunk << 7;
        if (chunk) __syncthreads();
        // stage A hi/lo (row-guarded) and B hi/lo, 16B per thread per iter
        #pragma unroll
        for (int i = 0; i < 8; i++) {
            int lin = tid + i * 256;
            int row = lin >> 4;
            int c8 = (lin & 15) << 3;
            uint4 vh = make_uint4(0, 0, 0, 0), vl = vh;
            int gr = m0 + row;
            if (gr < NN) {
                vh = *(const uint4*)(g_Ahi + (long)gr * 256 + kbase + c8);
                vl = *(const uint4*)(g_Alo + (long)gr * 256 + kbase + c8);
            }
            *(uint4*)(sAhi + row * SREG + c8) = vh;
            *(uint4*)(sAlo + row * SREG + c8) = vl;
            uint4 bh = *(const uint4*)(gB_hi + (long)row * 256 + kbase + c8);
            uint4 blv = *(const uint4*)(gB_lo + (long)row * 256 + kbase + c8);
            *(uint4*)(sBhi + row * SREG + c8) = bh;
            *(uint4*)(sBlo + row * SREG + c8) = blv;
        }
        __syncthreads();

        #pragma unroll
        for (int ks = 0; ks < 8; ks++) {
            int kcol = (ks << 4) + (t << 1);
            uint32_t ahi[4][4], alo[4][4];
            #pragma unroll
            for (int mf = 0; mf < 4; mf++) {
                int r = warp_m * 64 + mf * 16 + g;
                ahi[mf][0] = *(const uint32_t*)(sAhi + r * SREG + kcol);
                ahi[mf][1] = *(const uint32_t*)(sAhi + (r + 8) * SREG + kcol);
                ahi[mf][2] = *(const uint32_t*)(sAhi + r * SREG + kcol + 8);
                ahi[mf][3] = *(const uint32_t*)(sAhi + (r + 8) * SREG + kcol + 8);
                alo[mf][0] = *(const uint32_t*)(sAlo + r * SREG + kcol);
                alo[mf][1] = *(const uint32_t*)(sAlo + (r + 8) * SREG + kcol);
                alo[mf][2] = *(const uint32_t*)(sAlo + r * SREG + kcol + 8);
                alo[mf][3] = *(const uint32_t*)(sAlo + (r + 8) * SREG + kcol + 8);
            }
            uint32_t bhi[4][2], blo[4][2];
            #pragma unroll
            for (int nf = 0; nf < 4; nf++) {
                int nr = warp_n * 32 + nf * 8 + g;
                bhi[nf][0] = *(const uint32_t*)(sBhi + nr * SREG + kcol);
                bhi[nf][1] = *(const uint32_t*)(sBhi + nr * SREG + kcol + 8);
                blo[nf][0] = *(const uint32_t*)(sBlo + nr * SREG + kcol);
                blo[nf][1] = *(const uint32_t*)(sBlo + nr * SREG + kcol + 8);
            }
            #pragma unroll
            for (int mf = 0; mf < 4; mf++)
                #pragma unroll
                for (int nf = 0; nf < 4; nf++) {
                    mma16816(acc[mf][nf], ahi[mf], bhi[nf]);
                    mma16816(acc[mf][nf], ahi[mf], blo[nf]);
                    mma16816(acc[mf][nf], alo[mf], bhi[nf]);
                }
        }
    }

    // epilogue: bias + relu; write f32 h and (optionally) split bf16 A cols [128,256)
    #pragma unroll
    for (int nf = 0; nf < 4; nf++) {
        int col = warp_n * 32 + nf * 8 + (t << 1);
        float b0 = __ldg(&bl[col]);
        float b1 = __ldg(&bl[col + 1]);
        #pragma unroll
        for (int mf = 0; mf < 4; mf++) {
            int r0 = m0 + warp_m * 64 + mf * 16 + g;
            #pragma unroll
            for (int half = 0; half < 2; half++) {
                int r = r0 + half * 8;
                if (r < NN) {
                    float o0 = fmaxf(acc[mf][nf][half * 2 + 0] + b0, 0.f);
                    float o1 = fmaxf(acc[mf][nf][half * 2 + 1] + b1, 0.f);
                    *(float2*)(g_h + (long)r * D + col) = make_float2(o0, o1);
                    if (write_split) {
                        uint32_t hp, lp;
                        split2(o0, o1, hp, lp);
                        *(uint32_t*)(g_Ahi + (long)r * 256 + 128 + col) = hp;
                        *(uint32_t*)(g_Alo + (long)r * 256 + 128 + col) = lp;
                    }
                }
            }
        }
    }
}

// ---------------- final FC [128 -> 2]: warp per node ----------------
__global__ void k_fc(const float* __restrict__ fcW, const float* __restrict__ fcb,
                     float* __restrict__ out) {
    int gw = (blockIdx.x * blockDim.x + threadIdx.x) >> 5;
    if (gw >= NN) return;
    int lane = threadIdx.x & 31;
    const float* h = g_h + (long)gw * D;
    float4 v = *(const float4*)(h + (lane << 2));
    int k0 = lane << 2;
    float4 w01 = __ldg((const float4*)(fcW + k0 * 2));
    float4 w23 = __ldg((const float4*)(fcW + k0 * 2 + 4));
    float a0 = v.x * w01.x + v.y * w01.z + v.z * w23.x + v.w * w23.z;
    float a1 = v.x * w01.y + v.y * w01.w + v.z * w23.y + v.w * w23.w;
    #pragma unroll
    for (int d2 = 16; d2; d2 >>= 1) {
        a0 += __shfl_xor_sync(0xffffffffu, a0, d2);
        a1 += __shfl_xor_sync(0xffffffffu, a1, d2);
    }
    if (lane == 0) {
        out[2 * gw]     = a0 + __ldg(&fcb[0]);
        out[2 * gw + 1] = a1 + __ldg(&fcb[1]);
    }
}

// ---------------- launch ----------------
extern "C" void kernel_launch(void* const* d_in, const int* in_sizes, int n_in,
                              void* d_out, int out_size) {
    const float* x   = (const float*)d_in[0];
    const int*   ei  = (const int*)d_in[1];
    const float* Wl  = (const float*)d_in[2];
    const float* Wr  = (const float*)d_in[3];
    const float* bl  = (const float*)d_in[4];
    const float* fcW = (const float*)d_in[5];
    const float* fcb = (const float*)d_in[6];
    float* out = (float*)d_out;

    const int smem_bytes = SM_TOT_BF * 2;  // 139264
    cudaFuncSetAttribute(k_gemm_mma, cudaFuncAttributeMaxDynamicSharedMemorySize, smem_bytes);

    k_zero_deg<<<(NN + 255) / 256, 256>>>();
    k_count<<<(NE + 255) / 256, 256>>>(ei);
    k_prepw<<<(NL * 128 * 256 + 255) / 256, 256>>>(Wl, Wr);
    k_splitx<<<(NN * 32 + 255) / 256, 256>>>(x);
    k_scan<<<1, 1024>>>();
    k_initcursor<<<(NN + 255) / 256, 256>>>();
    k_fill<<<(NE + 255) / 256, 256>>>(ei);

    for (int l = 0; l < NL; l++) {
        k_agg<<<(NN * 32 + 255) / 256, 256>>>(x, l == 0);
        k_gemm_mma<<<NTILES, 256, smem_bytes>>>(l, l < NL - 1, bl + (long)l * D);
    }
    k_fc<<<(NN * 32 + 255) / 256, 256>>>(fcW, fcb, out);
}